// round 14
// baseline (speedup 1.0000x reference)
#include <cuda_runtime.h>
#include <cuda_bf16.h>
#include <cstdint>
#include <math.h>

// Problem constants
#define BB 8
#define TT 1024
#define EE 768
#define HH 12
#define DD 64
#define MM (BB*TT)        // 8192
#define E3 (3*EE)         // 2304

// Scratch (allocation-free rule: __device__ globals)
__device__ float g_qkv[(size_t)MM * E3];    // 75.5 MB (tf32-rounded)
__device__ float g_attn[(size_t)MM * EE];   // 25 MB   (tf32-rounded)

__device__ __forceinline__ uint32_t f2tf(float x) {
    uint32_t r;
    asm("cvt.rna.tf32.f32 %0, %1;" : "=r"(r) : "f"(x));
    return r;
}

__device__ __forceinline__ void cp16(void* smem_ptr, const void* gmem_ptr) {
    uint32_t s = (uint32_t)__cvta_generic_to_shared(smem_ptr);
    asm volatile("cp.async.cg.shared.global [%0], [%1], 16;\n"
                 :: "r"(s), "l"(gmem_ptr));
}
#define CP_COMMIT asm volatile("cp.async.commit_group;\n" ::: "memory")
#define CP_WAIT0  asm volatile("cp.async.wait_group 0;\n" ::: "memory")

__device__ __forceinline__ void mma_tf32(float c[4], const uint32_t a[4],
                                         uint32_t b0, uint32_t b1) {
    asm volatile(
        "mma.sync.aligned.m16n8k8.row.col.f32.tf32.tf32.f32 "
        "{%0,%1,%2,%3}, {%4,%5,%6,%7}, {%8,%9}, {%0,%1,%2,%3};\n"
        : "+f"(c[0]), "+f"(c[1]), "+f"(c[2]), "+f"(c[3])
        : "r"(a[0]), "r"(a[1]), "r"(a[2]), "r"(a[3]), "r"(b0), "r"(b1));
}

// ---------------------------------------------------------------------------
// Persistent GEMM: 128x128 tile, 4 warps (64x64), K-step 32, 2-stage
// cp.async, single-barrier pipeline, 3 CTAs/SM. tf32 rounding (rna) applied
// at FRAGMENT LOAD time -> raw fp32 inputs accepted; no pre-round pass.
// Bit-identical to the former pre-rounded path.
// ---------------------------------------------------------------------------
#define GA_STRIDE 36
#define GW_STRIDE 136
#define GA_WORDS (128 * GA_STRIDE)
#define GW_WORDS (32 * GW_STRIDE)
#define STG_WORDS (GA_WORDS + GW_WORDS)
#define GEMM_SMEM (2 * STG_WORDS * 4)
#define GK 768
#define GNK 24

template<int NX, int ROUND_OUT>
__global__ __launch_bounds__(128, 3) void gemm_bias_kernel(
    const float* __restrict__ A, const float* __restrict__ W,
    const float* __restrict__ bias, float* __restrict__ C)
{
    extern __shared__ float smem[];
    constexpr int NN = NX * 128;
    constexpr int NTILES = NX * (MM / 128);

    const int tid  = threadIdx.x;
    const int warp = tid >> 5, lane = tid & 31;
    const int wm   = (warp >> 1) * 64;
    const int wn   = (warp & 1) * 64;
    const int lr   = lane >> 2, lc = lane & 3;
    const int G    = gridDim.x;

    auto load_stage = [&](int s, int m0, int n0, int kk) {
        float* As = smem + s * STG_WORDS;
        float* Ws = As + GA_WORDS;
#pragma unroll
        for (int i = 0; i < 8; i++) {
            int idx = i * 128 + tid;
            int r = idx >> 3, c = (idx & 7) << 2;
            cp16(&As[r * GA_STRIDE + c], &A[(size_t)(m0 + r) * GK + kk + c]);
        }
#pragma unroll
        for (int i = 0; i < 8; i++) {
            int idx = i * 128 + tid;
            int r = idx >> 5, c = (idx & 31) << 2;
            cp16(&Ws[r * GW_STRIDE + c], &W[(size_t)(kk + r) * NN + n0 + c]);
        }
    };

    {
        int t0 = blockIdx.x;
        if (t0 < NTILES)
            load_stage(0, (t0 / NX) * 128, (t0 % NX) * 128, 0);
        CP_COMMIT;
    }

    for (int t = blockIdx.x; t < NTILES; t += G) {
        const int m0 = (t / NX) * 128;
        const int n0 = (t % NX) * 128;
        const int tn = t + G;

        float acc[4][8][4];
#pragma unroll
        for (int i = 0; i < 4; i++)
#pragma unroll
            for (int j = 0; j < 8; j++)
#pragma unroll
                for (int k = 0; k < 4; k++) acc[i][j][k] = 0.f;

        for (int kt = 0; kt < GNK; kt++) {
            const int s = kt & 1;
            CP_WAIT0;
            __syncthreads();
            if (kt + 1 < GNK) {
                load_stage(s ^ 1, m0, n0, (kt + 1) << 5);
            } else if (tn < NTILES) {
                load_stage(s ^ 1, (tn / NX) * 128, (tn % NX) * 128, 0);
            }
            CP_COMMIT;

            const float* As = smem + s * STG_WORDS;
            const float* Ws = As + GA_WORDS;
#pragma unroll
            for (int ks = 0; ks < 4; ks++) {
                const int kb = ks * 8;
                uint32_t a[4][4];
#pragma unroll
                for (int mt = 0; mt < 4; mt++) {
                    int mr = wm + mt * 16;
                    a[mt][0] = f2tf(As[(mr + lr) * GA_STRIDE + kb + lc]);
                    a[mt][1] = f2tf(As[(mr + lr + 8) * GA_STRIDE + kb + lc]);
                    a[mt][2] = f2tf(As[(mr + lr) * GA_STRIDE + kb + lc + 4]);
                    a[mt][3] = f2tf(As[(mr + lr + 8) * GA_STRIDE + kb + lc + 4]);
                }
#pragma unroll
                for (int half = 0; half < 2; half++) {
                    uint32_t b[4][2];
#pragma unroll
                    for (int j = 0; j < 4; j++) {
                        int nc = wn + (half * 4 + j) * 8;
                        b[j][0] = f2tf(Ws[(kb + lc) * GW_STRIDE + nc + lr]);
                        b[j][1] = f2tf(Ws[(kb + lc + 4) * GW_STRIDE + nc + lr]);
                    }
#pragma unroll
                    for (int mt = 0; mt < 4; mt++)
#pragma unroll
                        for (int j = 0; j < 4; j++)
                            mma_tf32(acc[mt][half * 4 + j], a[mt], b[j][0], b[j][1]);
                }
            }
        }

#pragma unroll
        for (int mt = 0; mt < 4; mt++) {
#pragma unroll
            for (int nt = 0; nt < 8; nt++) {
                int row = m0 + wm + mt * 16 + lr;
                int col = n0 + wn + nt * 8 + 2 * lc;
                float b0 = __ldg(&bias[col]), b1 = __ldg(&bias[col + 1]);
                float v0 = acc[mt][nt][0] + b0;
                float v1 = acc[mt][nt][1] + b1;
                float v2 = acc[mt][nt][2] + b0;
                float v3 = acc[mt][nt][3] + b1;
                if (ROUND_OUT) {
                    v0 = __uint_as_float(f2tf(v0));
                    v1 = __uint_as_float(f2tf(v1));
                    v2 = __uint_as_float(f2tf(v2));
                    v3 = __uint_as_float(f2tf(v3));
                }
                C[(size_t)row * NN + col]           = v0;
                C[(size_t)row * NN + col + 1]       = v1;
                C[(size_t)(row + 8) * NN + col]     = v2;
                C[(size_t)(row + 8) * NN + col + 1] = v3;
            }
        }
    }
}

// ---------------------------------------------------------------------------
// Flash attention v4 (R11 proven) + LPT block ordering: longest q-tiles
// (largest qt) launch first, so the 3.5-wave grid tail is filled by short
// blocks. 64 q-rows/block, 4 warps, Bc=64, shuffle-P, 3 CTAs/SM.
// ---------------------------------------------------------------------------
#define FQ_STRIDE 68
#define FV_STRIDE 72
#define FK_WORDS (64 * FQ_STRIDE)
#define FV_WORDS (64 * FV_STRIDE)
#define FLASH_SMEM ((2 * FK_WORDS + 2 * FV_WORDS) * 4)   // 71680 B

__global__ __launch_bounds__(128, 3) void flash_attn_kernel(
    const float* __restrict__ qkv, float* __restrict__ attn_out)
{
    extern __shared__ uint32_t sm[];
    float* Kraw = (float*)sm;                       // 2 stages [64][68]
    float* Vraw = (float*)(sm + 2 * FK_WORDS);      // 2 stages [64][72]

    const int b = blockIdx.z, h = blockIdx.y;
    const int qt = (TT / 64 - 1) - blockIdx.x;      // LPT: big qt first
    const int tid = threadIdx.x, warp = tid >> 5, lane = tid & 31;
    const int lr = lane >> 2, lc = lane & 3;

    const float* base = qkv + (size_t)b * TT * E3;
    const int qoff = h * DD, koff = EE + h * DD, voff = 2 * EE + h * DD;
    const int qrow0 = qt * 64;

    auto load_kv = [&](int s, int kt) {
        float* Kd = Kraw + s * FK_WORDS;
        float* Vd = Vraw + s * FV_WORDS;
#pragma unroll
        for (int i = 0; i < 8; i++) {
            int idx = i * 128 + tid;
            int r = idx >> 4, c = (idx & 15) << 2;
            size_t row = (size_t)(kt * 64 + r) * E3;
            cp16(&Kd[r * FQ_STRIDE + c], &base[row + koff + c]);
            cp16(&Vd[r * FV_STRIDE + c], &base[row + voff + c]);
        }
    };

    // Prologue: Q -> K stage-1 buffer (DMA), K0/V0 -> stage 0 (DMA).
    {
        float* Qtmp = Kraw + FK_WORDS;
#pragma unroll
        for (int i = 0; i < 8; i++) {
            int idx = i * 128 + tid;
            int r = idx >> 4, c = (idx & 15) << 2;
            cp16(&Qtmp[r * FQ_STRIDE + c],
                 &base[(size_t)(qrow0 + r) * E3 + qoff + c]);
        }
    }
    CP_COMMIT;
    load_kv(0, 0); CP_COMMIT;
    CP_WAIT0;
    __syncthreads();

    uint32_t aq[8][4];
    {
        const float* Qtmp = Kraw + FK_WORDS;
#pragma unroll
        for (int ks = 0; ks < 8; ks++) {
            aq[ks][0] = __float_as_uint(Qtmp[(warp * 16 + lr) * FQ_STRIDE + ks * 8 + lc] * 0.125f);
            aq[ks][1] = __float_as_uint(Qtmp[(warp * 16 + lr + 8) * FQ_STRIDE + ks * 8 + lc] * 0.125f);
            aq[ks][2] = __float_as_uint(Qtmp[(warp * 16 + lr) * FQ_STRIDE + ks * 8 + lc + 4] * 0.125f);
            aq[ks][3] = __float_as_uint(Qtmp[(warp * 16 + lr + 8) * FQ_STRIDE + ks * 8 + lc + 4] * 0.125f);
        }
    }

    float o[8][4];
#pragma unroll
    for (int i = 0; i < 8; i++)
#pragma unroll
        for (int j = 0; j < 4; j++) o[i][j] = 0.f;
    float m0r = -1e30f, m1r = -1e30f, l0 = 0.f, l1 = 0.f;

    for (int kt = 0; kt <= qt; kt++) {
        const int s = kt & 1;
        CP_WAIT0;
        __syncthreads();
        if (kt < qt) load_kv(s ^ 1, kt + 1);
        CP_COMMIT;

        const float* Kf = Kraw + s * FK_WORDS;
        const float* Vf = Vraw + s * FV_WORDS;

        float sv[8][4];
#pragma unroll
        for (int i = 0; i < 8; i++)
#pragma unroll
            for (int j = 0; j < 4; j++) sv[i][j] = 0.f;

#pragma unroll
        for (int nt = 0; nt < 8; nt++) {
#pragma unroll
            for (int ks = 0; ks < 8; ks++) {
                uint32_t b0 = __float_as_uint(Kf[(nt * 8 + lr) * FQ_STRIDE + ks * 8 + lc]);
                uint32_t b1 = __float_as_uint(Kf[(nt * 8 + lr) * FQ_STRIDE + ks * 8 + lc + 4]);
                mma_tf32(sv[nt], aq[ks], b0, b1);
            }
        }

        const int q0 = warp * 16 + lr, q1 = q0 + 8;
        if (kt == qt) {
#pragma unroll
            for (int nt = 0; nt < 8; nt++) {
                int c0 = nt * 8 + 2 * lc;
                if (c0     > q0) sv[nt][0] = -1e30f;
                if (c0 + 1 > q0) sv[nt][1] = -1e30f;
                if (c0     > q1) sv[nt][2] = -1e30f;
                if (c0 + 1 > q1) sv[nt][3] = -1e30f;
            }
        }

        float t0 = -1e30f, t1 = -1e30f;
#pragma unroll
        for (int nt = 0; nt < 8; nt++) {
            t0 = fmaxf(t0, fmaxf(sv[nt][0], sv[nt][1]));
            t1 = fmaxf(t1, fmaxf(sv[nt][2], sv[nt][3]));
        }
        t0 = fmaxf(t0, __shfl_xor_sync(0xffffffff, t0, 1));
        t0 = fmaxf(t0, __shfl_xor_sync(0xffffffff, t0, 2));
        t1 = fmaxf(t1, __shfl_xor_sync(0xffffffff, t1, 1));
        t1 = fmaxf(t1, __shfl_xor_sync(0xffffffff, t1, 2));

        float mn0 = fmaxf(m0r, t0), mn1 = fmaxf(m1r, t1);
        float al0 = __expf(m0r - mn0), al1 = __expf(m1r - mn1);
        m0r = mn0; m1r = mn1;

        float sum0 = 0.f, sum1 = 0.f;
#pragma unroll
        for (int nt = 0; nt < 8; nt++) {
            sv[nt][0] = __expf(sv[nt][0] - mn0);
            sv[nt][1] = __expf(sv[nt][1] - mn0);
            sv[nt][2] = __expf(sv[nt][2] - mn1);
            sv[nt][3] = __expf(sv[nt][3] - mn1);
            sum0 += sv[nt][0] + sv[nt][1];
            sum1 += sv[nt][2] + sv[nt][3];
        }
        sum0 += __shfl_xor_sync(0xffffffff, sum0, 1);
        sum0 += __shfl_xor_sync(0xffffffff, sum0, 2);
        sum1 += __shfl_xor_sync(0xffffffff, sum1, 1);
        sum1 += __shfl_xor_sync(0xffffffff, sum1, 2);
        l0 = l0 * al0 + sum0;
        l1 = l1 * al1 + sum1;

#pragma unroll
        for (int nt = 0; nt < 8; nt++) {
            o[nt][0] *= al0; o[nt][1] *= al0;
            o[nt][2] *= al1; o[nt][3] *= al1;
        }

        const int lsrc = (lane & 28) | (lc >> 1);
        const bool odd = (lc & 1);
#pragma unroll
        for (int ks = 0; ks < 8; ks++) {
            uint32_t p0 = f2tf(sv[ks][0]);
            uint32_t p1 = f2tf(sv[ks][1]);
            uint32_t p2 = f2tf(sv[ks][2]);
            uint32_t p3 = f2tf(sv[ks][3]);
            uint32_t q0v = __shfl_sync(0xffffffff, p0, lsrc);
            uint32_t q1v = __shfl_sync(0xffffffff, p1, lsrc);
            uint32_t q2v = __shfl_sync(0xffffffff, p2, lsrc);
            uint32_t q3v = __shfl_sync(0xffffffff, p3, lsrc);
            uint32_t u0v = __shfl_sync(0xffffffff, p0, lsrc + 2);
            uint32_t u1v = __shfl_sync(0xffffffff, p1, lsrc + 2);
            uint32_t u2v = __shfl_sync(0xffffffff, p2, lsrc + 2);
            uint32_t u3v = __shfl_sync(0xffffffff, p3, lsrc + 2);
            uint32_t ap[4];
            ap[0] = odd ? q1v : q0v;
            ap[1] = odd ? q3v : q2v;
            ap[2] = odd ? u1v : u0v;
            ap[3] = odd ? u3v : u2v;
#pragma unroll
            for (int nt = 0; nt < 8; nt++) {
                uint32_t b0 = __float_as_uint(Vf[(ks * 8 + lc) * FV_STRIDE + nt * 8 + lr]);
                uint32_t b1 = __float_as_uint(Vf[(ks * 8 + lc + 4) * FV_STRIDE + nt * 8 + lr]);
                mma_tf32(o[nt], ap, b0, b1);
            }
        }
    }

    const float inv0 = 1.f / l0, inv1 = 1.f / l1;
    const size_t row0 = (size_t)(b * TT + qrow0 + warp * 16 + lr) * EE + h * DD;
#pragma unroll
    for (int nt = 0; nt < 8; nt++) {
        int c = nt * 8 + 2 * lc;
        attn_out[row0 + c]              = __uint_as_float(f2tf(o[nt][0] * inv0));
        attn_out[row0 + c + 1]          = __uint_as_float(f2tf(o[nt][1] * inv0));
        attn_out[row0 + 8 * EE + c]     = __uint_as_float(f2tf(o[nt][2] * inv1));
        attn_out[row0 + 8 * EE + c + 1] = __uint_as_float(f2tf(o[nt][3] * inv1));
    }
}

// ---------------------------------------------------------------------------
extern "C" void kernel_launch(void* const* d_in, const int* in_sizes, int n_in,
                              void* d_out, int out_size)
{
    const float* x      = (const float*)d_in[0];
    const float* w_attn = (const float*)d_in[1];
    const float* b_attn = (const float*)d_in[2];
    const float* w_proj = (const float*)d_in[3];
    const float* b_proj = (const float*)d_in[4];
    float* out = (float*)d_out;

    float *qkv_ptr, *attn_ptr;
    cudaGetSymbolAddress((void**)&qkv_ptr, g_qkv);
    cudaGetSymbolAddress((void**)&attn_ptr, g_attn);

    cudaFuncSetAttribute(gemm_bias_kernel<18, 1>,
                         cudaFuncAttributeMaxDynamicSharedMemorySize, GEMM_SMEM);
    cudaFuncSetAttribute(gemm_bias_kernel<6, 0>,
                         cudaFuncAttributeMaxDynamicSharedMemorySize, GEMM_SMEM);
    cudaFuncSetAttribute(flash_attn_kernel,
                         cudaFuncAttributeMaxDynamicSharedMemorySize, FLASH_SMEM);

    // 1) QKV = x @ w_attn + b_attn [8192, 2304]; raw inputs, in-kernel tf32
    //    rounding; persistent 444-CTA grid; output tf32-rounded.
    gemm_bias_kernel<18, 1><<<444, 128, GEMM_SMEM>>>(x, w_attn, b_attn, qkv_ptr);

    // 2) causal flash attention (Br=64, shuffle-P, LPT order) -> g_attn
    flash_attn_kernel<<<dim3(TT / 64, HH, BB), 128, FLASH_SMEM>>>(qkv_ptr, attn_ptr);

    // 3) out = attn @ w_proj + b_proj [8192, 768]; raw w_proj, in-kernel cvt
    gemm_bias_kernel<6, 0><<<384, 128, GEMM_SMEM>>>(attn_ptr, w_proj, b_proj, out);
}

// round 15
// speedup vs baseline: 1.0556x; 1.0556x over previous
#include <cuda_runtime.h>
#include <cuda_bf16.h>
#include <cstdint>
#include <math.h>

// Problem constants
#define BB 8
#define TT 1024
#define EE 768
#define HH 12
#define DD 64
#define MM (BB*TT)        // 8192
#define E3 (3*EE)         // 2304

// Scratch (allocation-free rule: __device__ globals)
__device__ float g_qkv[(size_t)MM * E3];    // 75.5 MB (tf32-rounded)
__device__ float g_attn[(size_t)MM * EE];   // 25 MB   (tf32-rounded)
__device__ float g_x_tf[(size_t)MM * EE];   // 25 MB
__device__ float g_wa_tf[(size_t)EE * E3];  // 7.1 MB
__device__ float g_wp_tf[(size_t)EE * EE];  // 2.4 MB

__device__ __forceinline__ uint32_t f2tf(float x) {
    uint32_t r;
    asm("cvt.rna.tf32.f32 %0, %1;" : "=r"(r) : "f"(x));
    return r;
}

__device__ __forceinline__ void cp16(void* smem_ptr, const void* gmem_ptr) {
    uint32_t s = (uint32_t)__cvta_generic_to_shared(smem_ptr);
    asm volatile("cp.async.cg.shared.global [%0], [%1], 16;\n"
                 :: "r"(s), "l"(gmem_ptr));
}
#define CP_COMMIT asm volatile("cp.async.commit_group;\n" ::: "memory")
#define CP_WAIT0  asm volatile("cp.async.wait_group 0;\n" ::: "memory")

__device__ __forceinline__ void mma_tf32(float c[4], const uint32_t a[4],
                                         uint32_t b0, uint32_t b1) {
    asm volatile(
        "mma.sync.aligned.m16n8k8.row.col.f32.tf32.tf32.f32 "
        "{%0,%1,%2,%3}, {%4,%5,%6,%7}, {%8,%9}, {%0,%1,%2,%3};\n"
        : "+f"(c[0]), "+f"(c[1]), "+f"(c[2]), "+f"(c[3])
        : "r"(a[0]), "r"(a[1]), "r"(a[2]), "r"(a[3]), "r"(b0), "r"(b1));
}

// ---------------------------------------------------------------------------
// Merged tf32 pre-round for x, w_attn, w_proj (one launch)
// ---------------------------------------------------------------------------
#define N4_X  ((MM * EE) / 4)
#define N4_WA ((EE * E3) / 4)
#define N4_WP ((EE * EE) / 4)
__global__ __launch_bounds__(256) void cvt3_tf32_kernel(
    const float* __restrict__ x,  float* __restrict__ xo,
    const float* __restrict__ wa, float* __restrict__ wao,
    const float* __restrict__ wp, float* __restrict__ wpo)
{
    const int total = N4_X + N4_WA + N4_WP;
    int i = blockIdx.x * 256 + threadIdx.x;
    int stride = gridDim.x * 256;
    for (; i < total; i += stride) {
        const float4* src;
        float4* dst;
        int j = i;
        if (j < N4_X)            { src = (const float4*)x  + j; dst = (float4*)xo  + j; }
        else if ((j -= N4_X) < N4_WA) { src = (const float4*)wa + j; dst = (float4*)wao + j; }
        else { j -= N4_WA;         src = (const float4*)wp + j; dst = (float4*)wpo + j; }
        float4 v = *src;
        v.x = __uint_as_float(f2tf(v.x));
        v.y = __uint_as_float(f2tf(v.y));
        v.z = __uint_as_float(f2tf(v.z));
        v.w = __uint_as_float(f2tf(v.w));
        *dst = v;
    }
}

// ---------------------------------------------------------------------------
// Persistent GEMM (R11 proven): 128x128 tile, 4 warps (64x64), K-step 32,
// 2-stage cp.async, single-barrier pipeline, 3 CTAs/SM. Pre-rounded inputs,
// raw bit loads in the inner loop (no cvt in hot path).
// ---------------------------------------------------------------------------
#define GA_STRIDE 36
#define GW_STRIDE 136
#define GA_WORDS (128 * GA_STRIDE)
#define GW_WORDS (32 * GW_STRIDE)
#define STG_WORDS (GA_WORDS + GW_WORDS)
#define GEMM_SMEM (2 * STG_WORDS * 4)
#define GK 768
#define GNK 24

template<int NX, int ROUND_OUT>
__global__ __launch_bounds__(128, 3) void gemm_bias_kernel(
    const float* __restrict__ A, const float* __restrict__ W,
    const float* __restrict__ bias, float* __restrict__ C)
{
    extern __shared__ float smem[];
    constexpr int NN = NX * 128;
    constexpr int NTILES = NX * (MM / 128);

    const int tid  = threadIdx.x;
    const int warp = tid >> 5, lane = tid & 31;
    const int wm   = (warp >> 1) * 64;
    const int wn   = (warp & 1) * 64;
    const int lr   = lane >> 2, lc = lane & 3;
    const int G    = gridDim.x;

    auto load_stage = [&](int s, int m0, int n0, int kk) {
        float* As = smem + s * STG_WORDS;
        float* Ws = As + GA_WORDS;
#pragma unroll
        for (int i = 0; i < 8; i++) {
            int idx = i * 128 + tid;
            int r = idx >> 3, c = (idx & 7) << 2;
            cp16(&As[r * GA_STRIDE + c], &A[(size_t)(m0 + r) * GK + kk + c]);
        }
#pragma unroll
        for (int i = 0; i < 8; i++) {
            int idx = i * 128 + tid;
            int r = idx >> 5, c = (idx & 31) << 2;
            cp16(&Ws[r * GW_STRIDE + c], &W[(size_t)(kk + r) * NN + n0 + c]);
        }
    };

    {
        int t0 = blockIdx.x;
        if (t0 < NTILES)
            load_stage(0, (t0 / NX) * 128, (t0 % NX) * 128, 0);
        CP_COMMIT;
    }

    for (int t = blockIdx.x; t < NTILES; t += G) {
        const int m0 = (t / NX) * 128;
        const int n0 = (t % NX) * 128;
        const int tn = t + G;

        float acc[4][8][4];
#pragma unroll
        for (int i = 0; i < 4; i++)
#pragma unroll
            for (int j = 0; j < 8; j++)
#pragma unroll
                for (int k = 0; k < 4; k++) acc[i][j][k] = 0.f;

        for (int kt = 0; kt < GNK; kt++) {
            const int s = kt & 1;
            CP_WAIT0;
            __syncthreads();
            if (kt + 1 < GNK) {
                load_stage(s ^ 1, m0, n0, (kt + 1) << 5);
            } else if (tn < NTILES) {
                load_stage(s ^ 1, (tn / NX) * 128, (tn % NX) * 128, 0);
            }
            CP_COMMIT;

            const float* As = smem + s * STG_WORDS;
            const float* Ws = As + GA_WORDS;
#pragma unroll
            for (int ks = 0; ks < 4; ks++) {
                const int kb = ks * 8;
                uint32_t a[4][4];
#pragma unroll
                for (int mt = 0; mt < 4; mt++) {
                    int mr = wm + mt * 16;
                    a[mt][0] = __float_as_uint(As[(mr + lr) * GA_STRIDE + kb + lc]);
                    a[mt][1] = __float_as_uint(As[(mr + lr + 8) * GA_STRIDE + kb + lc]);
                    a[mt][2] = __float_as_uint(As[(mr + lr) * GA_STRIDE + kb + lc + 4]);
                    a[mt][3] = __float_as_uint(As[(mr + lr + 8) * GA_STRIDE + kb + lc + 4]);
                }
#pragma unroll
                for (int half = 0; half < 2; half++) {
                    uint32_t b[4][2];
#pragma unroll
                    for (int j = 0; j < 4; j++) {
                        int nc = wn + (half * 4 + j) * 8;
                        b[j][0] = __float_as_uint(Ws[(kb + lc) * GW_STRIDE + nc + lr]);
                        b[j][1] = __float_as_uint(Ws[(kb + lc + 4) * GW_STRIDE + nc + lr]);
                    }
#pragma unroll
                    for (int mt = 0; mt < 4; mt++)
#pragma unroll
                        for (int j = 0; j < 4; j++)
                            mma_tf32(acc[mt][half * 4 + j], a[mt], b[j][0], b[j][1]);
                }
            }
        }

#pragma unroll
        for (int mt = 0; mt < 4; mt++) {
#pragma unroll
            for (int nt = 0; nt < 8; nt++) {
                int row = m0 + wm + mt * 16 + lr;
                int col = n0 + wn + nt * 8 + 2 * lc;
                float b0 = __ldg(&bias[col]), b1 = __ldg(&bias[col + 1]);
                float v0 = acc[mt][nt][0] + b0;
                float v1 = acc[mt][nt][1] + b1;
                float v2 = acc[mt][nt][2] + b0;
                float v3 = acc[mt][nt][3] + b1;
                if (ROUND_OUT) {
                    v0 = __uint_as_float(f2tf(v0));
                    v1 = __uint_as_float(f2tf(v1));
                    v2 = __uint_as_float(f2tf(v2));
                    v3 = __uint_as_float(f2tf(v3));
                }
                C[(size_t)row * NN + col]           = v0;
                C[(size_t)row * NN + col + 1]       = v1;
                C[(size_t)(row + 8) * NN + col]     = v2;
                C[(size_t)(row + 8) * NN + col + 1] = v3;
            }
        }
    }
}

// ---------------------------------------------------------------------------
// Flash attention v4 (R11 proven) + LPT block ordering (longest q-tiles
// first). 64 q-rows/block, 4 warps, Bc=64, shuffle-P, 3 CTAs/SM.
// ---------------------------------------------------------------------------
#define FQ_STRIDE 68
#define FV_STRIDE 72
#define FK_WORDS (64 * FQ_STRIDE)
#define FV_WORDS (64 * FV_STRIDE)
#define FLASH_SMEM ((2 * FK_WORDS + 2 * FV_WORDS) * 4)   // 71680 B

__global__ __launch_bounds__(128, 3) void flash_attn_kernel(
    const float* __restrict__ qkv, float* __restrict__ attn_out)
{
    extern __shared__ uint32_t sm[];
    float* Kraw = (float*)sm;                       // 2 stages [64][68]
    float* Vraw = (float*)(sm + 2 * FK_WORDS);      // 2 stages [64][72]

    const int b = blockIdx.z, h = blockIdx.y;
    const int qt = (TT / 64 - 1) - blockIdx.x;      // LPT: big qt first
    const int tid = threadIdx.x, warp = tid >> 5, lane = tid & 31;
    const int lr = lane >> 2, lc = lane & 3;

    const float* base = qkv + (size_t)b * TT * E3;
    const int qoff = h * DD, koff = EE + h * DD, voff = 2 * EE + h * DD;
    const int qrow0 = qt * 64;

    auto load_kv = [&](int s, int kt) {
        float* Kd = Kraw + s * FK_WORDS;
        float* Vd = Vraw + s * FV_WORDS;
#pragma unroll
        for (int i = 0; i < 8; i++) {
            int idx = i * 128 + tid;
            int r = idx >> 4, c = (idx & 15) << 2;
            size_t row = (size_t)(kt * 64 + r) * E3;
            cp16(&Kd[r * FQ_STRIDE + c], &base[row + koff + c]);
            cp16(&Vd[r * FV_STRIDE + c], &base[row + voff + c]);
        }
    };

    // Prologue: Q -> K stage-1 buffer (DMA), K0/V0 -> stage 0 (DMA).
    {
        float* Qtmp = Kraw + FK_WORDS;
#pragma unroll
        for (int i = 0; i < 8; i++) {
            int idx = i * 128 + tid;
            int r = idx >> 4, c = (idx & 15) << 2;
            cp16(&Qtmp[r * FQ_STRIDE + c],
                 &base[(size_t)(qrow0 + r) * E3 + qoff + c]);
        }
    }
    CP_COMMIT;
    load_kv(0, 0); CP_COMMIT;
    CP_WAIT0;
    __syncthreads();

    uint32_t aq[8][4];
    {
        const float* Qtmp = Kraw + FK_WORDS;
#pragma unroll
        for (int ks = 0; ks < 8; ks++) {
            aq[ks][0] = __float_as_uint(Qtmp[(warp * 16 + lr) * FQ_STRIDE + ks * 8 + lc] * 0.125f);
            aq[ks][1] = __float_as_uint(Qtmp[(warp * 16 + lr + 8) * FQ_STRIDE + ks * 8 + lc] * 0.125f);
            aq[ks][2] = __float_as_uint(Qtmp[(warp * 16 + lr) * FQ_STRIDE + ks * 8 + lc + 4] * 0.125f);
            aq[ks][3] = __float_as_uint(Qtmp[(warp * 16 + lr + 8) * FQ_STRIDE + ks * 8 + lc + 4] * 0.125f);
        }
    }

    float o[8][4];
#pragma unroll
    for (int i = 0; i < 8; i++)
#pragma unroll
        for (int j = 0; j < 4; j++) o[i][j] = 0.f;
    float m0r = -1e30f, m1r = -1e30f, l0 = 0.f, l1 = 0.f;

    for (int kt = 0; kt <= qt; kt++) {
        const int s = kt & 1;
        CP_WAIT0;
        __syncthreads();
        if (kt < qt) load_kv(s ^ 1, kt + 1);
        CP_COMMIT;

        const float* Kf = Kraw + s * FK_WORDS;
        const float* Vf = Vraw + s * FV_WORDS;

        float sv[8][4];
#pragma unroll
        for (int i = 0; i < 8; i++)
#pragma unroll
            for (int j = 0; j < 4; j++) sv[i][j] = 0.f;

#pragma unroll
        for (int nt = 0; nt < 8; nt++) {
#pragma unroll
            for (int ks = 0; ks < 8; ks++) {
                uint32_t b0 = __float_as_uint(Kf[(nt * 8 + lr) * FQ_STRIDE + ks * 8 + lc]);
                uint32_t b1 = __float_as_uint(Kf[(nt * 8 + lr) * FQ_STRIDE + ks * 8 + lc + 4]);
                mma_tf32(sv[nt], aq[ks], b0, b1);
            }
        }

        const int q0 = warp * 16 + lr, q1 = q0 + 8;
        if (kt == qt) {
#pragma unroll
            for (int nt = 0; nt < 8; nt++) {
                int c0 = nt * 8 + 2 * lc;
                if (c0     > q0) sv[nt][0] = -1e30f;
                if (c0 + 1 > q0) sv[nt][1] = -1e30f;
                if (c0     > q1) sv[nt][2] = -1e30f;
                if (c0 + 1 > q1) sv[nt][3] = -1e30f;
            }
        }

        float t0 = -1e30f, t1 = -1e30f;
#pragma unroll
        for (int nt = 0; nt < 8; nt++) {
            t0 = fmaxf(t0, fmaxf(sv[nt][0], sv[nt][1]));
            t1 = fmaxf(t1, fmaxf(sv[nt][2], sv[nt][3]));
        }
        t0 = fmaxf(t0, __shfl_xor_sync(0xffffffff, t0, 1));
        t0 = fmaxf(t0, __shfl_xor_sync(0xffffffff, t0, 2));
        t1 = fmaxf(t1, __shfl_xor_sync(0xffffffff, t1, 1));
        t1 = fmaxf(t1, __shfl_xor_sync(0xffffffff, t1, 2));

        float mn0 = fmaxf(m0r, t0), mn1 = fmaxf(m1r, t1);
        float al0 = __expf(m0r - mn0), al1 = __expf(m1r - mn1);
        m0r = mn0; m1r = mn1;

        float sum0 = 0.f, sum1 = 0.f;
#pragma unroll
        for (int nt = 0; nt < 8; nt++) {
            sv[nt][0] = __expf(sv[nt][0] - mn0);
            sv[nt][1] = __expf(sv[nt][1] - mn0);
            sv[nt][2] = __expf(sv[nt][2] - mn1);
            sv[nt][3] = __expf(sv[nt][3] - mn1);
            sum0 += sv[nt][0] + sv[nt][1];
            sum1 += sv[nt][2] + sv[nt][3];
        }
        sum0 += __shfl_xor_sync(0xffffffff, sum0, 1);
        sum0 += __shfl_xor_sync(0xffffffff, sum0, 2);
        sum1 += __shfl_xor_sync(0xffffffff, sum1, 1);
        sum1 += __shfl_xor_sync(0xffffffff, sum1, 2);
        l0 = l0 * al0 + sum0;
        l1 = l1 * al1 + sum1;

#pragma unroll
        for (int nt = 0; nt < 8; nt++) {
            o[nt][0] *= al0; o[nt][1] *= al0;
            o[nt][2] *= al1; o[nt][3] *= al1;
        }

        const int lsrc = (lane & 28) | (lc >> 1);
        const bool odd = (lc & 1);
#pragma unroll
        for (int ks = 0; ks < 8; ks++) {
            uint32_t p0 = f2tf(sv[ks][0]);
            uint32_t p1 = f2tf(sv[ks][1]);
            uint32_t p2 = f2tf(sv[ks][2]);
            uint32_t p3 = f2tf(sv[ks][3]);
            uint32_t q0v = __shfl_sync(0xffffffff, p0, lsrc);
            uint32_t q1v = __shfl_sync(0xffffffff, p1, lsrc);
            uint32_t q2v = __shfl_sync(0xffffffff, p2, lsrc);
            uint32_t q3v = __shfl_sync(0xffffffff, p3, lsrc);
            uint32_t u0v = __shfl_sync(0xffffffff, p0, lsrc + 2);
            uint32_t u1v = __shfl_sync(0xffffffff, p1, lsrc + 2);
            uint32_t u2v = __shfl_sync(0xffffffff, p2, lsrc + 2);
            uint32_t u3v = __shfl_sync(0xffffffff, p3, lsrc + 2);
            uint32_t ap[4];
            ap[0] = odd ? q1v : q0v;
            ap[1] = odd ? q3v : q2v;
            ap[2] = odd ? u1v : u0v;
            ap[3] = odd ? u3v : u2v;
#pragma unroll
            for (int nt = 0; nt < 8; nt++) {
                uint32_t b0 = __float_as_uint(Vf[(ks * 8 + lc) * FV_STRIDE + nt * 8 + lr]);
                uint32_t b1 = __float_as_uint(Vf[(ks * 8 + lc + 4) * FV_STRIDE + nt * 8 + lr]);
                mma_tf32(o[nt], ap, b0, b1);
            }
        }
    }

    const float inv0 = 1.f / l0, inv1 = 1.f / l1;
    const size_t row0 = (size_t)(b * TT + qrow0 + warp * 16 + lr) * EE + h * DD;
#pragma unroll
    for (int nt = 0; nt < 8; nt++) {
        int c = nt * 8 + 2 * lc;
        attn_out[row0 + c]              = __uint_as_float(f2tf(o[nt][0] * inv0));
        attn_out[row0 + c + 1]          = __uint_as_float(f2tf(o[nt][1] * inv0));
        attn_out[row0 + 8 * EE + c]     = __uint_as_float(f2tf(o[nt][2] * inv1));
        attn_out[row0 + 8 * EE + c + 1] = __uint_as_float(f2tf(o[nt][3] * inv1));
    }
}

// ---------------------------------------------------------------------------
extern "C" void kernel_launch(void* const* d_in, const int* in_sizes, int n_in,
                              void* d_out, int out_size)
{
    const float* x      = (const float*)d_in[0];
    const float* w_attn = (const float*)d_in[1];
    const float* b_attn = (const float*)d_in[2];
    const float* w_proj = (const float*)d_in[3];
    const float* b_proj = (const float*)d_in[4];
    float* out = (float*)d_out;

    float *qkv_ptr, *attn_ptr, *xtf, *watf, *wptf;
    cudaGetSymbolAddress((void**)&qkv_ptr, g_qkv);
    cudaGetSymbolAddress((void**)&attn_ptr, g_attn);
    cudaGetSymbolAddress((void**)&xtf,  g_x_tf);
    cudaGetSymbolAddress((void**)&watf, g_wa_tf);
    cudaGetSymbolAddress((void**)&wptf, g_wp_tf);

    cudaFuncSetAttribute(gemm_bias_kernel<18, 1>,
                         cudaFuncAttributeMaxDynamicSharedMemorySize, GEMM_SMEM);
    cudaFuncSetAttribute(gemm_bias_kernel<6, 0>,
                         cudaFuncAttributeMaxDynamicSharedMemorySize, GEMM_SMEM);
    cudaFuncSetAttribute(flash_attn_kernel,
                         cudaFuncAttributeMaxDynamicSharedMemorySize, FLASH_SMEM);

    // 0) pre-round inputs to the tf32 grid (single launch)
    cvt3_tf32_kernel<<<888, 256>>>(x, xtf, w_attn, watf, w_proj, wptf);

    // 1) QKV = x @ w_attn + b_attn [8192, 2304], persistent 444-CTA grid
    gemm_bias_kernel<18, 1><<<444, 128, GEMM_SMEM>>>(xtf, watf, b_attn, qkv_ptr);

    // 2) causal flash attention (Br=64, shuffle-P, LPT order) -> g_attn
    flash_attn_kernel<<<dim3(TT / 64, HH, BB), 128, FLASH_SMEM>>>(qkv_ptr, attn_ptr);

    // 3) out = attn @ w_proj + b_proj [8192, 768] (persistent single wave)
    gemm_bias_kernel<6, 0><<<384, 128, GEMM_SMEM>>>(attn_ptr, w_proj, b_proj, out);
}

// round 16
// speedup vs baseline: 1.7478x; 1.6558x over previous
#include <cuda_runtime.h>
#include <cuda_fp16.h>
#include <cstdint>
#include <math.h>

// Problem constants
#define BB 8
#define TT 1024
#define EE 768
#define HH 12
#define DD 64
#define MM (BB*TT)        // 8192
#define E3 (3*EE)         // 2304

// Scratch (allocation-free rule: __device__ globals)
__device__ __half g_qkv_h[(size_t)MM * E3];   // 37.7 MB
__device__ __half g_attn_h[(size_t)MM * EE];  // 12.6 MB
__device__ __half g_x_h[(size_t)MM * EE];     // 12.6 MB
__device__ __half g_wa_t[(size_t)E3 * EE];    // 3.5 MB  w_attn^T [2304][768]
__device__ __half g_wp_t[(size_t)EE * EE];    // 1.2 MB  w_proj^T [768][768]

__device__ __forceinline__ void cp16(void* smem_ptr, const void* gmem_ptr) {
    uint32_t s = (uint32_t)__cvta_generic_to_shared(smem_ptr);
    asm volatile("cp.async.cg.shared.global [%0], [%1], 16;\n"
                 :: "r"(s), "l"(gmem_ptr));
}
#define CP_COMMIT asm volatile("cp.async.commit_group;\n" ::: "memory")
#define CP_WAIT0  asm volatile("cp.async.wait_group 0;\n" ::: "memory")

__device__ __forceinline__ uint32_t h2u(float lo, float hi) {
    __half2 h = __floats2half2_rn(lo, hi);
    return *reinterpret_cast<uint32_t*>(&h);
}
__device__ __forceinline__ uint32_t hh2u(__half lo, __half hi) {
    __half2 h = __halves2half2(lo, hi);
    return *reinterpret_cast<uint32_t*>(&h);
}

// fp16 MMA m16n8k16, fp32 accumulate
__device__ __forceinline__ void mma_f16(float c[4], const uint32_t a[4],
                                        uint32_t b0, uint32_t b1) {
    asm volatile(
        "mma.sync.aligned.m16n8k16.row.col.f32.f16.f16.f32 "
        "{%0,%1,%2,%3}, {%4,%5,%6,%7}, {%8,%9}, {%0,%1,%2,%3};\n"
        : "+f"(c[0]), "+f"(c[1]), "+f"(c[2]), "+f"(c[3])
        : "r"(a[0]), "r"(a[1]), "r"(a[2]), "r"(a[3]), "r"(b0), "r"(b1));
}

// ---------------------------------------------------------------------------
// fp32 -> fp16 convert (x)
// ---------------------------------------------------------------------------
__global__ __launch_bounds__(256) void cvt_h_kernel(
    const float* __restrict__ in, __half* __restrict__ out, int n4)
{
    int i = blockIdx.x * 256 + threadIdx.x;
    int stride = gridDim.x * 256;
    for (; i < n4; i += stride) {
        float4 v = ((const float4*)in)[i];
        ((__half2*)out)[2 * i]     = __floats2half2_rn(v.x, v.y);
        ((__half2*)out)[2 * i + 1] = __floats2half2_rn(v.z, v.w);
    }
}

// ---------------------------------------------------------------------------
// Transpose + fp16 convert: out[c][r] = half(in[r][c]).  in: R x C.
// ---------------------------------------------------------------------------
__global__ __launch_bounds__(256) void transpose_h_kernel(
    const float* __restrict__ in, __half* __restrict__ out, int R, int C)
{
    __shared__ float t[32][33];
    int bx = blockIdx.x * 32, by = blockIdx.y * 32;
    int tx = threadIdx.x, ty = threadIdx.y;
#pragma unroll
    for (int i = 0; i < 32; i += 8)
        t[ty + i][tx] = in[(size_t)(by + ty + i) * C + bx + tx];
    __syncthreads();
#pragma unroll
    for (int i = 0; i < 32; i += 8)
        out[(size_t)(bx + ty + i) * R + by + tx] = __float2half_rn(t[tx][ty + i]);
}

// ---------------------------------------------------------------------------
// Persistent fp16 GEMM: C[M, NX*128] = A[M,768] @ Wt[N,768]^T + bias
// CTA 128x128, 4 warps (64x64), K-step 64 halves (4 k16 chunks), 2-stage
// cp.async, single-barrier pipeline, 3 CTAs/SM. A,Bt are K-major fp16.
// smem rows: 64 halves = 32 u32 + 4 pad = 36 u32 -> frag loads conflict-free.
// ---------------------------------------------------------------------------
#define GS32 36
#define GT_WORDS (128 * GS32)              // 4608 u32 per tile (A or B)
#define GSTG_WORDS (2 * GT_WORDS)          // 9216 u32 per stage (A+B)
#define GEMM_SMEM (2 * GSTG_WORDS * 4)     // 73728 B -> 3 CTAs/SM
#define GKH 768
#define GNKH 12                            // 768 / 64

template<int NX, int OUT_HALF>
__global__ __launch_bounds__(128, 3) void gemm_h_kernel(
    const __half* __restrict__ A, const __half* __restrict__ Bt,
    const float* __restrict__ bias, void* __restrict__ Cout)
{
    extern __shared__ uint32_t smem[];
    constexpr int NN = NX * 128;
    constexpr int NTILES = NX * (MM / 128);

    const int tid  = threadIdx.x;
    const int warp = tid >> 5, lane = tid & 31;
    const int wm   = (warp >> 1) * 64;
    const int wn   = (warp & 1) * 64;
    const int lr   = lane >> 2, lc = lane & 3;
    const int G    = gridDim.x;

    auto load_stage = [&](int s, int m0, int n0, int kk) {
        uint32_t* As = smem + s * GSTG_WORDS;
        uint32_t* Bs = As + GT_WORDS;
#pragma unroll
        for (int i = 0; i < 8; i++) {            // A: 1024 16B chunks
            int idx = i * 128 + tid;
            int r = idx >> 3, c = idx & 7;
            cp16(&As[r * GS32 + c * 4], &A[(size_t)(m0 + r) * GKH + kk + c * 8]);
        }
#pragma unroll
        for (int i = 0; i < 8; i++) {            // Bt: 1024 16B chunks
            int idx = i * 128 + tid;
            int r = idx >> 3, c = idx & 7;
            cp16(&Bs[r * GS32 + c * 4], &Bt[(size_t)(n0 + r) * GKH + kk + c * 8]);
        }
    };

    {
        int t0 = blockIdx.x;
        if (t0 < NTILES)
            load_stage(0, (t0 / NX) * 128, (t0 % NX) * 128, 0);
        CP_COMMIT;
    }

    for (int t = blockIdx.x; t < NTILES; t += G) {
        const int m0 = (t / NX) * 128;
        const int n0 = (t % NX) * 128;
        const int tn = t + G;

        float acc[4][8][4];
#pragma unroll
        for (int i = 0; i < 4; i++)
#pragma unroll
            for (int j = 0; j < 8; j++)
#pragma unroll
                for (int k = 0; k < 4; k++) acc[i][j][k] = 0.f;

        for (int kt = 0; kt < GNKH; kt++) {
            const int s = kt & 1;
            CP_WAIT0;
            __syncthreads();
            if (kt + 1 < GNKH) {
                load_stage(s ^ 1, m0, n0, (kt + 1) * 64);
            } else if (tn < NTILES) {
                load_stage(s ^ 1, (tn / NX) * 128, (tn % NX) * 128, 0);
            }
            CP_COMMIT;

            const uint32_t* As = smem + s * GSTG_WORDS;
            const uint32_t* Bs = As + GT_WORDS;
#pragma unroll
            for (int j = 0; j < 4; j++) {        // k16 chunks
                const int kb = 8 * j;
                uint32_t a[4][4];
#pragma unroll
                for (int mt = 0; mt < 4; mt++) {
                    int mr = wm + mt * 16;
                    a[mt][0] = As[(mr + lr) * GS32 + kb + lc];
                    a[mt][1] = As[(mr + lr + 8) * GS32 + kb + lc];
                    a[mt][2] = As[(mr + lr) * GS32 + kb + lc + 4];
                    a[mt][3] = As[(mr + lr + 8) * GS32 + kb + lc + 4];
                }
#pragma unroll
                for (int half_ = 0; half_ < 2; half_++) {
                    uint32_t b[4][2];
#pragma unroll
                    for (int jj = 0; jj < 4; jj++) {
                        int nr = wn + (half_ * 4 + jj) * 8 + lr;
                        b[jj][0] = Bs[nr * GS32 + kb + lc];
                        b[jj][1] = Bs[nr * GS32 + kb + lc + 4];
                    }
#pragma unroll
                    for (int mt = 0; mt < 4; mt++)
#pragma unroll
                        for (int jj = 0; jj < 4; jj++)
                            mma_f16(acc[mt][half_ * 4 + jj], a[mt],
                                    b[jj][0], b[jj][1]);
                }
            }
        }

        // Epilogue
#pragma unroll
        for (int mt = 0; mt < 4; mt++) {
#pragma unroll
            for (int nt = 0; nt < 8; nt++) {
                int row = m0 + wm + mt * 16 + lr;
                int col = n0 + wn + nt * 8 + 2 * lc;
                float b0 = __ldg(&bias[col]), b1 = __ldg(&bias[col + 1]);
                float v0 = acc[mt][nt][0] + b0;
                float v1 = acc[mt][nt][1] + b1;
                float v2 = acc[mt][nt][2] + b0;
                float v3 = acc[mt][nt][3] + b1;
                if (OUT_HALF) {
                    __half* C = (__half*)Cout;
                    *(__half2*)&C[(size_t)row * NN + col] =
                        __floats2half2_rn(v0, v1);
                    *(__half2*)&C[(size_t)(row + 8) * NN + col] =
                        __floats2half2_rn(v2, v3);
                } else {
                    float* C = (float*)Cout;
                    C[(size_t)row * NN + col]           = v0;
                    C[(size_t)row * NN + col + 1]       = v1;
                    C[(size_t)(row + 8) * NN + col]     = v2;
                    C[(size_t)(row + 8) * NN + col + 1] = v3;
                }
            }
        }
    }
}

// ---------------------------------------------------------------------------
// fp16 flash attention, causal. 64 q-rows/block, 4 warps, Bc=64.
// S = Q@K^T via m16n8k16 (K b-frags = contiguous-k u32 from natural layout).
// P packs SAME-LANE from S c-frags (no shuffles). PV B from V via LDS.16.
// Q staged through K stage-1. smem 36.9 KB -> 4 CTAs/SM.
// ---------------------------------------------------------------------------
#define FS32 36                            // 64 halves + 8 pad = 36 u32 rows
#define FT_WORDS (64 * FS32)               // 2304 u32 per tile
#define FLASH_SMEM (4 * FT_WORDS * 4)      // 36864 B

__global__ __launch_bounds__(128, 4) void flash_attn_kernel(
    const __half* __restrict__ qkv, __half* __restrict__ attn_out)
{
    extern __shared__ uint32_t sm[];
    uint32_t* Ks = sm;                      // 2 stages [64][36]
    uint32_t* Vs = sm + 2 * FT_WORDS;       // 2 stages [64][36]

    const int b = blockIdx.z, h = blockIdx.y;
    const int qt = (TT / 64 - 1) - blockIdx.x;   // LPT
    const int tid = threadIdx.x, warp = tid >> 5, lane = tid & 31;
    const int lr = lane >> 2, lc = lane & 3;

    const __half* base = qkv + (size_t)b * TT * E3;
    const int qoff = h * DD, koff = EE + h * DD, voff = 2 * EE + h * DD;
    const int qrow0 = qt * 64;

    auto load_kv = [&](int s, int kt) {
        uint32_t* Kd = Ks + s * FT_WORDS;
        uint32_t* Vd = Vs + s * FT_WORDS;
#pragma unroll
        for (int i = 0; i < 4; i++) {       // K: 512 chunks
            int idx = i * 128 + tid;
            int r = idx >> 3, c = idx & 7;
            cp16(&Kd[r * FS32 + c * 4],
                 &base[(size_t)(kt * 64 + r) * E3 + koff + c * 8]);
        }
#pragma unroll
        for (int i = 0; i < 4; i++) {       // V: 512 chunks
            int idx = i * 128 + tid;
            int r = idx >> 3, c = idx & 7;
            cp16(&Vd[r * FS32 + c * 4],
                 &base[(size_t)(kt * 64 + r) * E3 + voff + c * 8]);
        }
    };

    // Prologue: Q -> K stage-1 (DMA); K0/V0 -> stage 0 (DMA)
    {
        uint32_t* Qd = Ks + FT_WORDS;
#pragma unroll
        for (int i = 0; i < 4; i++) {
            int idx = i * 128 + tid;
            int r = idx >> 3, c = idx & 7;
            cp16(&Qd[r * FS32 + c * 4],
                 &base[(size_t)(qrow0 + r) * E3 + qoff + c * 8]);
        }
    }
    CP_COMMIT;
    load_kv(0, 0); CP_COMMIT;
    CP_WAIT0;
    __syncthreads();

    // Hoist Q fragments (own 16 rows), scaled by 0.125 (exact in fp16)
    uint32_t aq[4][4];
    {
        const uint32_t* Qd = Ks + FT_WORDS;
        const __half2 sc = __floats2half2_rn(0.125f, 0.125f);
#pragma unroll
        for (int j = 0; j < 4; j++) {
            const int kb = 8 * j;
            uint32_t t0 = Qd[(warp * 16 + lr) * FS32 + kb + lc];
            uint32_t t1 = Qd[(warp * 16 + lr + 8) * FS32 + kb + lc];
            uint32_t t2 = Qd[(warp * 16 + lr) * FS32 + kb + lc + 4];
            uint32_t t3 = Qd[(warp * 16 + lr + 8) * FS32 + kb + lc + 4];
            __half2 h0 = __hmul2(*(__half2*)&t0, sc);
            __half2 h1 = __hmul2(*(__half2*)&t1, sc);
            __half2 h2v = __hmul2(*(__half2*)&t2, sc);
            __half2 h3 = __hmul2(*(__half2*)&t3, sc);
            aq[j][0] = *(uint32_t*)&h0;
            aq[j][1] = *(uint32_t*)&h1;
            aq[j][2] = *(uint32_t*)&h2v;
            aq[j][3] = *(uint32_t*)&h3;
        }
    }

    float o[8][4];
#pragma unroll
    for (int i = 0; i < 8; i++)
#pragma unroll
        for (int j = 0; j < 4; j++) o[i][j] = 0.f;
    float m0r = -1e30f, m1r = -1e30f, l0 = 0.f, l1 = 0.f;

    for (int kt = 0; kt <= qt; kt++) {
        const int s = kt & 1;
        CP_WAIT0;
        __syncthreads();                 // (kt=0: protects Q buffer reads)
        if (kt < qt) load_kv(s ^ 1, kt + 1);
        CP_COMMIT;

        const uint32_t* Kf = Ks + s * FT_WORDS;
        const __half*   Vh = (const __half*)(Vs + s * FT_WORDS);

        // S = Q @ K^T
        float sv[8][4];
#pragma unroll
        for (int i = 0; i < 8; i++)
#pragma unroll
            for (int j = 0; j < 4; j++) sv[i][j] = 0.f;

#pragma unroll
        for (int nt = 0; nt < 8; nt++) {
            const int tok = nt * 8 + lr;
#pragma unroll
            for (int j = 0; j < 4; j++) {
                uint32_t b0 = Kf[tok * FS32 + 8 * j + lc];
                uint32_t b1 = Kf[tok * FS32 + 8 * j + lc + 4];
                mma_f16(sv[nt], aq[j], b0, b1);
            }
        }

        // Causal mask (diagonal tile only)
        const int q0 = warp * 16 + lr, q1 = q0 + 8;
        if (kt == qt) {
#pragma unroll
            for (int nt = 0; nt < 8; nt++) {
                int c0 = nt * 8 + 2 * lc;
                if (c0     > q0) sv[nt][0] = -1e30f;
                if (c0 + 1 > q0) sv[nt][1] = -1e30f;
                if (c0     > q1) sv[nt][2] = -1e30f;
                if (c0 + 1 > q1) sv[nt][3] = -1e30f;
            }
        }

        // Online softmax (fp32, unchanged)
        float t0 = -1e30f, t1 = -1e30f;
#pragma unroll
        for (int nt = 0; nt < 8; nt++) {
            t0 = fmaxf(t0, fmaxf(sv[nt][0], sv[nt][1]));
            t1 = fmaxf(t1, fmaxf(sv[nt][2], sv[nt][3]));
        }
        t0 = fmaxf(t0, __shfl_xor_sync(0xffffffff, t0, 1));
        t0 = fmaxf(t0, __shfl_xor_sync(0xffffffff, t0, 2));
        t1 = fmaxf(t1, __shfl_xor_sync(0xffffffff, t1, 1));
        t1 = fmaxf(t1, __shfl_xor_sync(0xffffffff, t1, 2));

        float mn0 = fmaxf(m0r, t0), mn1 = fmaxf(m1r, t1);
        float al0 = __expf(m0r - mn0), al1 = __expf(m1r - mn1);
        m0r = mn0; m1r = mn1;

        float sum0 = 0.f, sum1 = 0.f;
#pragma unroll
        for (int nt = 0; nt < 8; nt++) {
            sv[nt][0] = __expf(sv[nt][0] - mn0);
            sv[nt][1] = __expf(sv[nt][1] - mn0);
            sv[nt][2] = __expf(sv[nt][2] - mn1);
            sv[nt][3] = __expf(sv[nt][3] - mn1);
            sum0 += sv[nt][0] + sv[nt][1];
            sum1 += sv[nt][2] + sv[nt][3];
        }
        sum0 += __shfl_xor_sync(0xffffffff, sum0, 1);
        sum0 += __shfl_xor_sync(0xffffffff, sum0, 2);
        sum1 += __shfl_xor_sync(0xffffffff, sum1, 1);
        sum1 += __shfl_xor_sync(0xffffffff, sum1, 2);
        l0 = l0 * al0 + sum0;
        l1 = l1 * al1 + sum1;

#pragma unroll
        for (int nt = 0; nt < 8; nt++) {
            o[nt][0] *= al0; o[nt][1] *= al0;
            o[nt][2] *= al1; o[nt][3] *= al1;
        }

        // O += P @ V.  fp16 PV a-frags pack SAME-LANE from S c-frags.
#pragma unroll
        for (int j = 0; j < 4; j++) {       // token chunks of 16
            uint32_t ap[4];
            ap[0] = h2u(sv[2 * j][0],     sv[2 * j][1]);
            ap[1] = h2u(sv[2 * j][2],     sv[2 * j][3]);
            ap[2] = h2u(sv[2 * j + 1][0], sv[2 * j + 1][1]);
            ap[3] = h2u(sv[2 * j + 1][2], sv[2 * j + 1][3]);
            const int tb = 16 * j + 2 * lc;
#pragma unroll
            for (int nt = 0; nt < 8; nt++) {
                const int d = nt * 8 + lr;
                uint32_t b0 = hh2u(Vh[tb * 72 + d],       Vh[(tb + 1) * 72 + d]);
                uint32_t b1 = hh2u(Vh[(tb + 8) * 72 + d], Vh[(tb + 9) * 72 + d]);
                mma_f16(o[nt], ap, b0, b1);
            }
        }
    }

    // Epilogue: normalize, store fp16
    const float inv0 = 1.f / l0, inv1 = 1.f / l1;
    const size_t row0 = (size_t)(b * TT + qrow0 + warp * 16 + lr) * EE + h * DD;
#pragma unroll
    for (int nt = 0; nt < 8; nt++) {
        int c = nt * 8 + 2 * lc;
        *(__half2*)&attn_out[row0 + c] =
            __floats2half2_rn(o[nt][0] * inv0, o[nt][1] * inv0);
        *(__half2*)&attn_out[row0 + 8 * EE + c] =
            __floats2half2_rn(o[nt][2] * inv1, o[nt][3] * inv1);
    }
}

// ---------------------------------------------------------------------------
extern "C" void kernel_launch(void* const* d_in, const int* in_sizes, int n_in,
                              void* d_out, int out_size)
{
    const float* x      = (const float*)d_in[0];
    const float* w_attn = (const float*)d_in[1];
    const float* b_attn = (const float*)d_in[2];
    const float* w_proj = (const float*)d_in[3];
    const float* b_proj = (const float*)d_in[4];
    float* out = (float*)d_out;

    __half *qkvh, *attnh, *xh, *wat, *wpt;
    cudaGetSymbolAddress((void**)&qkvh,  g_qkv_h);
    cudaGetSymbolAddress((void**)&attnh, g_attn_h);
    cudaGetSymbolAddress((void**)&xh,    g_x_h);
    cudaGetSymbolAddress((void**)&wat,   g_wa_t);
    cudaGetSymbolAddress((void**)&wpt,   g_wp_t);

    cudaFuncSetAttribute(gemm_h_kernel<18, 1>,
                         cudaFuncAttributeMaxDynamicSharedMemorySize, GEMM_SMEM);
    cudaFuncSetAttribute(gemm_h_kernel<6, 0>,
                         cudaFuncAttributeMaxDynamicSharedMemorySize, GEMM_SMEM);
    cudaFuncSetAttribute(flash_attn_kernel,
                         cudaFuncAttributeMaxDynamicSharedMemorySize, FLASH_SMEM);

    // 0) convert x -> fp16; transpose+convert weights to [N][K] fp16
    cvt_h_kernel<<<888, 256>>>(x, xh, (MM * EE) / 4);
    transpose_h_kernel<<<dim3(E3 / 32, EE / 32), dim3(32, 8)>>>(w_attn, wat, EE, E3);
    transpose_h_kernel<<<dim3(EE / 32, EE / 32), dim3(32, 8)>>>(w_proj, wpt, EE, EE);

    // 1) QKV = x @ w_attn + b_attn [8192, 2304] fp16 out, persistent 444 CTAs
    gemm_h_kernel<18, 1><<<444, 128, GEMM_SMEM>>>(xh, wat, b_attn, qkvh);

    // 2) causal fp16 flash attention -> g_attn_h
    flash_attn_kernel<<<dim3(TT / 64, HH, BB), 128, FLASH_SMEM>>>(qkvh, attnh);

    // 3) out = attn @ w_proj + b_proj [8192, 768], fp32 out
    gemm_h_kernel<6, 0><<<384, 128, GEMM_SMEM>>>(attnh, wpt, b_proj, out);
}

// round 17
// speedup vs baseline: 1.8479x; 1.0573x over previous
#include <cuda_runtime.h>
#include <cuda_fp16.h>
#include <cstdint>
#include <math.h>

// Problem constants
#define BB 8
#define TT 1024
#define EE 768
#define HH 12
#define DD 64
#define MM (BB*TT)        // 8192
#define E3 (3*EE)         // 2304

// Scratch (allocation-free rule: __device__ globals)
__device__ __half g_qkv_h[(size_t)MM * E3];   // 37.7 MB
__device__ __half g_attn_h[(size_t)MM * EE];  // 12.6 MB
__device__ __half g_x_h[(size_t)MM * EE];     // 12.6 MB
__device__ __half g_wa_t[(size_t)E3 * EE];    // 3.5 MB  w_attn^T [2304][768]
__device__ __half g_wp_t[(size_t)EE * EE];    // 1.2 MB  w_proj^T [768][768]

__device__ __forceinline__ void cp16(void* smem_ptr, const void* gmem_ptr) {
    uint32_t s = (uint32_t)__cvta_generic_to_shared(smem_ptr);
    asm volatile("cp.async.cg.shared.global [%0], [%1], 16;\n"
                 :: "r"(s), "l"(gmem_ptr));
}
#define CP_COMMIT asm volatile("cp.async.commit_group;\n" ::: "memory")
#define CP_WAIT0  asm volatile("cp.async.wait_group 0;\n" ::: "memory")

__device__ __forceinline__ uint32_t h2u(float lo, float hi) {
    __half2 h = __floats2half2_rn(lo, hi);
    return *reinterpret_cast<uint32_t*>(&h);
}

// fp16 MMA m16n8k16, fp32 accumulate
__device__ __forceinline__ void mma_f16(float c[4], const uint32_t a[4],
                                        uint32_t b0, uint32_t b1) {
    asm volatile(
        "mma.sync.aligned.m16n8k16.row.col.f32.f16.f16.f32 "
        "{%0,%1,%2,%3}, {%4,%5,%6,%7}, {%8,%9}, {%0,%1,%2,%3};\n"
        : "+f"(c[0]), "+f"(c[1]), "+f"(c[2]), "+f"(c[3])
        : "r"(a[0]), "r"(a[1]), "r"(a[2]), "r"(a[3]), "r"(b0), "r"(b1));
}

__device__ __forceinline__ void ldsm_x4(uint32_t r[4], uint32_t addr) {
    asm volatile("ldmatrix.sync.aligned.m8n8.x4.shared.b16 {%0,%1,%2,%3}, [%4];"
                 : "=r"(r[0]), "=r"(r[1]), "=r"(r[2]), "=r"(r[3]) : "r"(addr));
}
__device__ __forceinline__ void ldsm_x4_trans(uint32_t r[4], uint32_t addr) {
    asm volatile("ldmatrix.sync.aligned.m8n8.x4.trans.shared.b16 {%0,%1,%2,%3}, [%4];"
                 : "=r"(r[0]), "=r"(r[1]), "=r"(r[2]), "=r"(r[3]) : "r"(addr));
}

// ---------------------------------------------------------------------------
// fp32 -> fp16 convert (x)
// ---------------------------------------------------------------------------
__global__ __launch_bounds__(256) void cvt_h_kernel(
    const float* __restrict__ in, __half* __restrict__ out, int n4)
{
    int i = blockIdx.x * 256 + threadIdx.x;
    int stride = gridDim.x * 256;
    for (; i < n4; i += stride) {
        float4 v = ((const float4*)in)[i];
        ((__half2*)out)[2 * i]     = __floats2half2_rn(v.x, v.y);
        ((__half2*)out)[2 * i + 1] = __floats2half2_rn(v.z, v.w);
    }
}

// ---------------------------------------------------------------------------
// Transpose + fp16 convert: out[c][r] = half(in[r][c]).  in: R x C.
// ---------------------------------------------------------------------------
__global__ __launch_bounds__(256) void transpose_h_kernel(
    const float* __restrict__ in, __half* __restrict__ out, int R, int C)
{
    __shared__ float t[32][33];
    int bx = blockIdx.x * 32, by = blockIdx.y * 32;
    int tx = threadIdx.x, ty = threadIdx.y;
#pragma unroll
    for (int i = 0; i < 32; i += 8)
        t[ty + i][tx] = in[(size_t)(by + ty + i) * C + bx + tx];
    __syncthreads();
#pragma unroll
    for (int i = 0; i < 32; i += 8)
        out[(size_t)(bx + ty + i) * R + by + tx] = __float2half_rn(t[tx][ty + i]);
}

// ---------------------------------------------------------------------------
// Persistent fp16 GEMM (R16 proven, unchanged): CTA 128x128, 4 warps (64x64),
// K-step 64 halves, 2-stage cp.async, single-barrier pipeline, 3 CTAs/SM.
// ---------------------------------------------------------------------------
#define GS32 36
#define GT_WORDS (128 * GS32)
#define GSTG_WORDS (2 * GT_WORDS)
#define GEMM_SMEM (2 * GSTG_WORDS * 4)
#define GKH 768
#define GNKH 12

template<int NX, int OUT_HALF>
__global__ __launch_bounds__(128, 3) void gemm_h_kernel(
    const __half* __restrict__ A, const __half* __restrict__ Bt,
    const float* __restrict__ bias, void* __restrict__ Cout)
{
    extern __shared__ uint32_t smem[];
    constexpr int NN = NX * 128;
    constexpr int NTILES = NX * (MM / 128);

    const int tid  = threadIdx.x;
    const int warp = tid >> 5, lane = tid & 31;
    const int wm   = (warp >> 1) * 64;
    const int wn   = (warp & 1) * 64;
    const int lr   = lane >> 2, lc = lane & 3;
    const int G    = gridDim.x;

    auto load_stage = [&](int s, int m0, int n0, int kk) {
        uint32_t* As = smem + s * GSTG_WORDS;
        uint32_t* Bs = As + GT_WORDS;
#pragma unroll
        for (int i = 0; i < 8; i++) {
            int idx = i * 128 + tid;
            int r = idx >> 3, c = idx & 7;
            cp16(&As[r * GS32 + c * 4], &A[(size_t)(m0 + r) * GKH + kk + c * 8]);
        }
#pragma unroll
        for (int i = 0; i < 8; i++) {
            int idx = i * 128 + tid;
            int r = idx >> 3, c = idx & 7;
            cp16(&Bs[r * GS32 + c * 4], &Bt[(size_t)(n0 + r) * GKH + kk + c * 8]);
        }
    };

    {
        int t0 = blockIdx.x;
        if (t0 < NTILES)
            load_stage(0, (t0 / NX) * 128, (t0 % NX) * 128, 0);
        CP_COMMIT;
    }

    for (int t = blockIdx.x; t < NTILES; t += G) {
        const int m0 = (t / NX) * 128;
        const int n0 = (t % NX) * 128;
        const int tn = t + G;

        float acc[4][8][4];
#pragma unroll
        for (int i = 0; i < 4; i++)
#pragma unroll
            for (int j = 0; j < 8; j++)
#pragma unroll
                for (int k = 0; k < 4; k++) acc[i][j][k] = 0.f;

        for (int kt = 0; kt < GNKH; kt++) {
            const int s = kt & 1;
            CP_WAIT0;
            __syncthreads();
            if (kt + 1 < GNKH) {
                load_stage(s ^ 1, m0, n0, (kt + 1) * 64);
            } else if (tn < NTILES) {
                load_stage(s ^ 1, (tn / NX) * 128, (tn % NX) * 128, 0);
            }
            CP_COMMIT;

            const uint32_t* As = smem + s * GSTG_WORDS;
            const uint32_t* Bs = As + GT_WORDS;
#pragma unroll
            for (int j = 0; j < 4; j++) {
                const int kb = 8 * j;
                uint32_t a[4][4];
#pragma unroll
                for (int mt = 0; mt < 4; mt++) {
                    int mr = wm + mt * 16;
                    a[mt][0] = As[(mr + lr) * GS32 + kb + lc];
                    a[mt][1] = As[(mr + lr + 8) * GS32 + kb + lc];
                    a[mt][2] = As[(mr + lr) * GS32 + kb + lc + 4];
                    a[mt][3] = As[(mr + lr + 8) * GS32 + kb + lc + 4];
                }
#pragma unroll
                for (int half_ = 0; half_ < 2; half_++) {
                    uint32_t b[4][2];
#pragma unroll
                    for (int jj = 0; jj < 4; jj++) {
                        int nr = wn + (half_ * 4 + jj) * 8 + lr;
                        b[jj][0] = Bs[nr * GS32 + kb + lc];
                        b[jj][1] = Bs[nr * GS32 + kb + lc + 4];
                    }
#pragma unroll
                    for (int mt = 0; mt < 4; mt++)
#pragma unroll
                        for (int jj = 0; jj < 4; jj++)
                            mma_f16(acc[mt][half_ * 4 + jj], a[mt],
                                    b[jj][0], b[jj][1]);
                }
            }
        }

#pragma unroll
        for (int mt = 0; mt < 4; mt++) {
#pragma unroll
            for (int nt = 0; nt < 8; nt++) {
                int row = m0 + wm + mt * 16 + lr;
                int col = n0 + wn + nt * 8 + 2 * lc;
                float b0 = __ldg(&bias[col]), b1 = __ldg(&bias[col + 1]);
                float v0 = acc[mt][nt][0] + b0;
                float v1 = acc[mt][nt][1] + b1;
                float v2 = acc[mt][nt][2] + b0;
                float v3 = acc[mt][nt][3] + b1;
                if (OUT_HALF) {
                    __half* C = (__half*)Cout;
                    *(__half2*)&C[(size_t)row * NN + col] =
                        __floats2half2_rn(v0, v1);
                    *(__half2*)&C[(size_t)(row + 8) * NN + col] =
                        __floats2half2_rn(v2, v3);
                } else {
                    float* C = (float*)Cout;
                    C[(size_t)row * NN + col]           = v0;
                    C[(size_t)row * NN + col + 1]       = v1;
                    C[(size_t)(row + 8) * NN + col]     = v2;
                    C[(size_t)(row + 8) * NN + col + 1] = v3;
                }
            }
        }
    }
}

// ---------------------------------------------------------------------------
// fp16 flash attention, causal. 64 q-rows/block, 4 warps, Bc=64.
// K b-frags via ldmatrix.x4 (non-trans); V b-frags via ldmatrix.x4.trans
// (replaces 128 scalar LDS.16/warp-iter). P packs same-lane from S c-frags.
// Q staged through K stage-1. smem 36.9 KB -> 4 CTAs/SM.
// ---------------------------------------------------------------------------
#define FS32 36                            // 64 halves + 8 pad = 36 u32 rows
#define FT_WORDS (64 * FS32)               // 2304 u32 per tile
#define FLASH_SMEM (4 * FT_WORDS * 4)      // 36864 B

__global__ __launch_bounds__(128, 4) void flash_attn_kernel(
    const __half* __restrict__ qkv, __half* __restrict__ attn_out)
{
    extern __shared__ uint32_t sm[];
    uint32_t* Ks = sm;                      // 2 stages [64][36]
    uint32_t* Vs = sm + 2 * FT_WORDS;       // 2 stages [64][36]

    const int b = blockIdx.z, h = blockIdx.y;
    const int qt = (TT / 64 - 1) - blockIdx.x;   // LPT
    const int tid = threadIdx.x, warp = tid >> 5, lane = tid & 31;
    const int lr = lane >> 2, lc = lane & 3;

    const __half* base = qkv + (size_t)b * TT * E3;
    const int qoff = h * DD, koff = EE + h * DD, voff = 2 * EE + h * DD;
    const int qrow0 = qt * 64;

    auto load_kv = [&](int s, int kt) {
        uint32_t* Kd = Ks + s * FT_WORDS;
        uint32_t* Vd = Vs + s * FT_WORDS;
#pragma unroll
        for (int i = 0; i < 4; i++) {
            int idx = i * 128 + tid;
            int r = idx >> 3, c = idx & 7;
            cp16(&Kd[r * FS32 + c * 4],
                 &base[(size_t)(kt * 64 + r) * E3 + koff + c * 8]);
        }
#pragma unroll
        for (int i = 0; i < 4; i++) {
            int idx = i * 128 + tid;
            int r = idx >> 3, c = idx & 7;
            cp16(&Vd[r * FS32 + c * 4],
                 &base[(size_t)(kt * 64 + r) * E3 + voff + c * 8]);
        }
    };

    // Prologue: Q -> K stage-1 (DMA); K0/V0 -> stage 0 (DMA)
    {
        uint32_t* Qd = Ks + FT_WORDS;
#pragma unroll
        for (int i = 0; i < 4; i++) {
            int idx = i * 128 + tid;
            int r = idx >> 3, c = idx & 7;
            cp16(&Qd[r * FS32 + c * 4],
                 &base[(size_t)(qrow0 + r) * E3 + qoff + c * 8]);
        }
    }
    CP_COMMIT;
    load_kv(0, 0); CP_COMMIT;
    CP_WAIT0;
    __syncthreads();

    // Hoist Q fragments (own 16 rows), scaled by 0.125 (exact in fp16)
    uint32_t aq[4][4];
    {
        const uint32_t* Qd = Ks + FT_WORDS;
        const __half2 sc = __floats2half2_rn(0.125f, 0.125f);
#pragma unroll
        for (int j = 0; j < 4; j++) {
            const int kb = 8 * j;
            uint32_t t0 = Qd[(warp * 16 + lr) * FS32 + kb + lc];
            uint32_t t1 = Qd[(warp * 16 + lr + 8) * FS32 + kb + lc];
            uint32_t t2 = Qd[(warp * 16 + lr) * FS32 + kb + lc + 4];
            uint32_t t3 = Qd[(warp * 16 + lr + 8) * FS32 + kb + lc + 4];
            __half2 h0 = __hmul2(*(__half2*)&t0, sc);
            __half2 h1 = __hmul2(*(__half2*)&t1, sc);
            __half2 h2v = __hmul2(*(__half2*)&t2, sc);
            __half2 h3 = __hmul2(*(__half2*)&t3, sc);
            aq[j][0] = *(uint32_t*)&h0;
            aq[j][1] = *(uint32_t*)&h1;
            aq[j][2] = *(uint32_t*)&h2v;
            aq[j][3] = *(uint32_t*)&h3;
        }
    }

    float o[8][4];
#pragma unroll
    for (int i = 0; i < 8; i++)
#pragma unroll
        for (int j = 0; j < 4; j++) o[i][j] = 0.f;
    float m0r = -1e30f, m1r = -1e30f, l0 = 0.f, l1 = 0.f;

    // ldmatrix per-lane address components (in halves)
    const int lrow = lane & 15;             // token row within 16-block
    const int lqhi = (lane >> 1) & 8;       // +8 for lanes 16-31
    const int lq   = (lane >> 3) * 8;       // 0,8,16,24 by quadrant

    for (int kt = 0; kt <= qt; kt++) {
        const int s = kt & 1;
        CP_WAIT0;
        __syncthreads();                 // (kt=0: protects Q buffer reads)
        if (kt < qt) load_kv(s ^ 1, kt + 1);
        CP_COMMIT;

        const __half* Kh = (const __half*)(Ks + s * FT_WORDS);
        const __half* Vh = (const __half*)(Vs + s * FT_WORDS);

        // S = Q @ K^T.  K b-frags via ldmatrix.x4 non-trans:
        // quadrant q covers k block 8q; rows = tokens nt*8 + (lane&7).
        float sv[8][4];
#pragma unroll
        for (int i = 0; i < 8; i++)
#pragma unroll
            for (int j = 0; j < 4; j++) sv[i][j] = 0.f;

#pragma unroll
        for (int nt = 0; nt < 8; nt++) {
            const uint32_t rowa = (uint32_t)__cvta_generic_to_shared(
                &Kh[(nt * 8 + (lane & 7)) * 72]);
#pragma unroll
            for (int jp = 0; jp < 2; jp++) {
                uint32_t bv[4];
                ldsm_x4(bv, rowa + (32 * jp + lq) * 2);
                mma_f16(sv[nt], aq[2 * jp],     bv[0], bv[1]);
                mma_f16(sv[nt], aq[2 * jp + 1], bv[2], bv[3]);
            }
        }

        // Causal mask (diagonal tile only)
        const int q0 = warp * 16 + lr, q1 = q0 + 8;
        if (kt == qt) {
#pragma unroll
            for (int nt = 0; nt < 8; nt++) {
                int c0 = nt * 8 + 2 * lc;
                if (c0     > q0) sv[nt][0] = -1e30f;
                if (c0 + 1 > q0) sv[nt][1] = -1e30f;
                if (c0     > q1) sv[nt][2] = -1e30f;
                if (c0 + 1 > q1) sv[nt][3] = -1e30f;
            }
        }

        // Online softmax (fp32)
        float t0 = -1e30f, t1 = -1e30f;
#pragma unroll
        for (int nt = 0; nt < 8; nt++) {
            t0 = fmaxf(t0, fmaxf(sv[nt][0], sv[nt][1]));
            t1 = fmaxf(t1, fmaxf(sv[nt][2], sv[nt][3]));
        }
        t0 = fmaxf(t0, __shfl_xor_sync(0xffffffff, t0, 1));
        t0 = fmaxf(t0, __shfl_xor_sync(0xffffffff, t0, 2));
        t1 = fmaxf(t1, __shfl_xor_sync(0xffffffff, t1, 1));
        t1 = fmaxf(t1, __shfl_xor_sync(0xffffffff, t1, 2));

        float mn0 = fmaxf(m0r, t0), mn1 = fmaxf(m1r, t1);
        float al0 = __expf(m0r - mn0), al1 = __expf(m1r - mn1);
        m0r = mn0; m1r = mn1;

        float sum0 = 0.f, sum1 = 0.f;
#pragma unroll
        for (int nt = 0; nt < 8; nt++) {
            sv[nt][0] = __expf(sv[nt][0] - mn0);
            sv[nt][1] = __expf(sv[nt][1] - mn0);
            sv[nt][2] = __expf(sv[nt][2] - mn1);
            sv[nt][3] = __expf(sv[nt][3] - mn1);
            sum0 += sv[nt][0] + sv[nt][1];
            sum1 += sv[nt][2] + sv[nt][3];
        }
        sum0 += __shfl_xor_sync(0xffffffff, sum0, 1);
        sum0 += __shfl_xor_sync(0xffffffff, sum0, 2);
        sum1 += __shfl_xor_sync(0xffffffff, sum1, 1);
        sum1 += __shfl_xor_sync(0xffffffff, sum1, 2);
        l0 = l0 * al0 + sum0;
        l1 = l1 * al1 + sum1;

#pragma unroll
        for (int nt = 0; nt < 8; nt++) {
            o[nt][0] *= al0; o[nt][1] *= al0;
            o[nt][2] *= al1; o[nt][3] *= al1;
        }

        // O += P @ V.  P packs same-lane; V b-frags via ldmatrix.x4.trans:
        // rows = tokens 16j + (lane&15); d block = 16ntp + (+8 for lanes>=16).
#pragma unroll
        for (int j = 0; j < 4; j++) {
            uint32_t ap[4];
            ap[0] = h2u(sv[2 * j][0],     sv[2 * j][1]);
            ap[1] = h2u(sv[2 * j][2],     sv[2 * j][3]);
            ap[2] = h2u(sv[2 * j + 1][0], sv[2 * j + 1][1]);
            ap[3] = h2u(sv[2 * j + 1][2], sv[2 * j + 1][3]);
            const uint32_t rowv = (uint32_t)__cvta_generic_to_shared(
                &Vh[(16 * j + lrow) * 72 + lqhi]);
#pragma unroll
            for (int ntp = 0; ntp < 4; ntp++) {
                uint32_t bv[4];
                ldsm_x4_trans(bv, rowv + (16 * ntp) * 2);
                mma_f16(o[2 * ntp],     ap, bv[0], bv[1]);
                mma_f16(o[2 * ntp + 1], ap, bv[2], bv[3]);
            }
        }
    }

    // Epilogue: normalize, store fp16
    const float inv0 = 1.f / l0, inv1 = 1.f / l1;
    const size_t row0 = (size_t)(b * TT + qrow0 + warp * 16 + lr) * EE + h * DD;
#pragma unroll
    for (int nt = 0; nt < 8; nt++) {
        int c = nt * 8 + 2 * lc;
        *(__half2*)&attn_out[row0 + c] =
            __floats2half2_rn(o[nt][0] * inv0, o[nt][1] * inv0);
        *(__half2*)&attn_out[row0 + 8 * EE + c] =
            __floats2half2_rn(o[nt][2] * inv1, o[nt][3] * inv1);
    }
}

// ---------------------------------------------------------------------------
extern "C" void kernel_launch(void* const* d_in, const int* in_sizes, int n_in,
                              void* d_out, int out_size)
{
    const float* x      = (const float*)d_in[0];
    const float* w_attn = (const float*)d_in[1];
    const float* b_attn = (const float*)d_in[2];
    const float* w_proj = (const float*)d_in[3];
    const float* b_proj = (const float*)d_in[4];
    float* out = (float*)d_out;

    __half *qkvh, *attnh, *xh, *wat, *wpt;
    cudaGetSymbolAddress((void**)&qkvh,  g_qkv_h);
    cudaGetSymbolAddress((void**)&attnh, g_attn_h);
    cudaGetSymbolAddress((void**)&xh,    g_x_h);
    cudaGetSymbolAddress((void**)&wat,   g_wa_t);
    cudaGetSymbolAddress((void**)&wpt,   g_wp_t);

    cudaFuncSetAttribute(gemm_h_kernel<18, 1>,
                         cudaFuncAttributeMaxDynamicSharedMemorySize, GEMM_SMEM);
    cudaFuncSetAttribute(gemm_h_kernel<6, 0>,
                         cudaFuncAttributeMaxDynamicSharedMemorySize, GEMM_SMEM);
    cudaFuncSetAttribute(flash_attn_kernel,
                         cudaFuncAttributeMaxDynamicSharedMemorySize, FLASH_SMEM);

    // 0) convert x -> fp16; transpose+convert weights to [N][K] fp16
    cvt_h_kernel<<<888, 256>>>(x, xh, (MM * EE) / 4);
    transpose_h_kernel<<<dim3(E3 / 32, EE / 32), dim3(32, 8)>>>(w_attn, wat, EE, E3);
    transpose_h_kernel<<<dim3(EE / 32, EE / 32), dim3(32, 8)>>>(w_proj, wpt, EE, EE);

    // 1) QKV = x @ w_attn + b_attn [8192, 2304] fp16 out, persistent 444 CTAs
    gemm_h_kernel<18, 1><<<444, 128, GEMM_SMEM>>>(xh, wat, b_attn, qkvh);

    // 2) causal fp16 flash attention (ldmatrix K/V frags) -> g_attn_h
    flash_attn_kernel<<<dim3(TT / 64, HH, BB), 128, FLASH_SMEM>>>(qkvh, attnh);

    // 3) out = attn @ w_proj + b_proj [8192, 768], fp32 out
    gemm_h_kernel<6, 0><<<384, 128, GEMM_SMEM>>>(attnh, wpt, b_proj, out);
}